// round 1
// baseline (speedup 1.0000x reference)
#include <cuda_runtime.h>
#include <math.h>

#define HW   262144
#define DD   256
#define VV   32
#define NF   256
#define NPART 512

// ---------------- scratch (device globals; no allocs in kernel_launch) ----
__device__ float g_iv2[DD*VV];
__device__ float g_nw2[DD*VV];      // -2 * W * iv2
__device__ float g_c[VV];           // sum_d W^2 * iv2
__device__ float g_Q[HW*VV];        // 32 MB, normalized responsibilities
__device__ float g_Mpart[NPART*DD*VV]; // 16 MB partials of X^T Q
__device__ float g_spart[NPART*VV];
__device__ float g_M[DD*VV];
__device__ float g_s[VV];
__device__ float g_Z[DD*VV];
__device__ float g_Adj[VV*VV];
__device__ float g_T1[VV*NF];
__device__ float g_Zo[VV*NF];

// ---------------- packed f32x2 helpers -----------------------------------
typedef unsigned long long ull;
__device__ __forceinline__ ull pk2(float lo, float hi){
    ull r; asm("mov.b64 %0,{%1,%2};" : "=l"(r) : "f"(lo), "f"(hi)); return r;
}
__device__ __forceinline__ float2 up2(ull v){
    float2 r; asm("mov.b64 {%0,%1},%2;" : "=f"(r.x), "=f"(r.y) : "l"(v)); return r;
}
__device__ __forceinline__ ull f2fma(ull a, ull b, ull c){
    ull d; asm("fma.rn.f32x2 %0,%1,%2,%3;" : "=l"(d) : "l"(a), "l"(b), "l"(c)); return d;
}

// ---------------- kernel 0: precompute tables ----------------------------
__global__ void k_prep(const float* __restrict__ W, const float* __restrict__ var){
    int e = blockIdx.x*256 + threadIdx.x;   // 32 blocks x 256 = 8192
    float iv  = 1.0f / var[e];
    float iv2 = iv*iv;
    g_iv2[e] = iv2;
    g_nw2[e] = -2.0f * W[e] * iv2;
}
__global__ void k_prep_c(const float* __restrict__ W){
    int v = threadIdx.x;                    // 1 block x 32
    float c = 0.0f;
    for(int d=0; d<DD; d++){
        float w = W[d*VV+v];
        c = fmaf(w*w, g_iv2[d*VV+v], c);
    }
    g_c[v] = c;
}

// ---------------- kernel 1a: Q pass (fused 2 GEMMs + softmax) -------------
// grid 1024, block 128; each block: 256 points, each thread: 2 points.
__global__ __launch_bounds__(128) void k_qpass(const float* __restrict__ X){
    __shared__ __align__(16) float ivc[32*VV];   // d-chunk of iv2
    __shared__ __align__(16) float nwc[32*VV];   // d-chunk of -2*W*iv2
    __shared__ float xs[256*33];                 // 256 pts x 32 d, pad 1
    __shared__ float c_s[VV];

    const int tid = threadIdx.x;
    const int pbase = blockIdx.x * 256;
    if(tid < VV) c_s[tid] = g_c[tid];

    ull q0[16], q1[16];
    #pragma unroll
    for(int i=0;i<16;i++){ q0[i]=0ull; q1[i]=0ull; }

    for(int ch=0; ch<8; ch++){
        __syncthreads();
        // stage table chunk (2048 entries)
        #pragma unroll
        for(int i=tid; i<32*VV; i+=128){
            ivc[i] = g_iv2[ch*32*VV + i];
            nwc[i] = g_nw2[ch*32*VV + i];
        }
        // stage X chunk: 256 pts x 32 d, coalesced
        #pragma unroll
        for(int i=tid; i<256*32; i+=128){
            int pl = i >> 5, dl = i & 31;
            xs[pl*33 + dl] = X[(pbase+pl)*DD + ch*32 + dl];
        }
        __syncthreads();

        #pragma unroll 4
        for(int d=0; d<32; d++){
            float x0 = xs[tid*33 + d];
            float x1 = xs[(tid+128)*33 + d];
            ull x0p = pk2(x0,x0), x1p = pk2(x1,x1);
            const ulonglong2* arow = (const ulonglong2*)(ivc + d*VV);
            const ulonglong2* brow = (const ulonglong2*)(nwc + d*VV);
            #pragma unroll
            for(int j=0;j<8;j++){
                ulonglong2 a = arow[j];
                ulonglong2 b = brow[j];
                ull t;
                t = f2fma(x0p, a.x, b.x); q0[2*j  ] = f2fma(x0p, t, q0[2*j  ]);
                t = f2fma(x0p, a.y, b.y); q0[2*j+1] = f2fma(x0p, t, q0[2*j+1]);
                t = f2fma(x1p, a.x, b.x); q1[2*j  ] = f2fma(x1p, t, q1[2*j  ]);
                t = f2fma(x1p, a.y, b.y); q1[2*j+1] = f2fma(x1p, t, q1[2*j+1]);
            }
        }
    }

    // epilogue: min-shift, exp, normalize, store
#define Q_EPILOGUE(QARR, POFF)                                                 \
    {                                                                          \
        int p = pbase + tid + (POFF);                                          \
        float qa[32];                                                          \
        _Pragma("unroll")                                                      \
        for(int j=0;j<16;j++){                                                 \
            float2 f = up2(QARR[j]);                                           \
            qa[2*j]   = f.x + c_s[2*j];                                        \
            qa[2*j+1] = f.y + c_s[2*j+1];                                      \
        }                                                                      \
        float mn = qa[0];                                                      \
        _Pragma("unroll")                                                      \
        for(int v=1;v<32;v++) mn = fminf(mn, qa[v]);                           \
        float sum = 0.0f;                                                      \
        _Pragma("unroll")                                                      \
        for(int v=0;v<32;v++){ float e = __expf(-0.5f*(qa[v]-mn)); qa[v]=e; sum+=e; } \
        float inv = 1.0f / sum;                                                \
        float4* dst = (float4*)(g_Q + (size_t)p*VV);                           \
        _Pragma("unroll")                                                      \
        for(int j=0;j<8;j++)                                                   \
            dst[j] = make_float4(qa[4*j]*inv, qa[4*j+1]*inv,                   \
                                 qa[4*j+2]*inv, qa[4*j+3]*inv);                \
    }
    Q_EPILOGUE(q0, 0)
    Q_EPILOGUE(q1, 128)
#undef Q_EPILOGUE
}

// ---------------- kernel 1b: M = X^T Q partials, s = colsum(Q) ------------
// grid 512, block 256 (thread owns d = tid); 512 points per block.
__global__ __launch_bounds__(256) void k_mpass(const float* __restrict__ X){
    __shared__ __align__(16) float qs[8*VV];
    __shared__ float sred[256];
    const int tid = threadIdx.x;
    const int pbase = blockIdx.x * 512;

    ull m[16];
    #pragma unroll
    for(int i=0;i<16;i++) m[i]=0ull;
    float sacc = 0.0f;

    for(int b=0;b<64;b++){
        __syncthreads();
        float qv = g_Q[(size_t)(pbase + b*8 + (tid>>5))*VV + (tid&31)];
        qs[tid] = qv;
        sacc += qv;
        __syncthreads();
        const float* xp = X + (pbase + b*8)*DD + tid;
        #pragma unroll
        for(int p=0;p<8;p++){
            float xv = xp[p*DD];        // coalesced across tid
            ull xpk = pk2(xv,xv);
            const ulonglong2* qrow = (const ulonglong2*)(qs + p*VV);
            #pragma unroll
            for(int j=0;j<8;j++){
                ulonglong2 qq = qrow[j];
                m[2*j  ] = f2fma(xpk, qq.x, m[2*j  ]);
                m[2*j+1] = f2fma(xpk, qq.y, m[2*j+1]);
            }
        }
    }
    float* mp = g_Mpart + (size_t)blockIdx.x*DD*VV + tid*VV;
    #pragma unroll
    for(int j=0;j<16;j++){ float2 f = up2(m[j]); mp[2*j]=f.x; mp[2*j+1]=f.y; }

    sred[tid] = sacc;
    __syncthreads();
    if(tid < VV){
        float ssum = 0.0f;
        #pragma unroll
        for(int g=0; g<8; g++) ssum += sred[g*32 + tid];
        g_spart[blockIdx.x*VV + tid] = ssum;
    }
}

// ---------------- kernel 2a: deterministic reduction of partials ----------
__global__ void k_reduce(){
    if(blockIdx.x < 32){
        int e = blockIdx.x*256 + threadIdx.x;
        float s = 0.0f;
        for(int part=0; part<NPART; part++) s += g_Mpart[(size_t)part*DD*VV + e];
        g_M[e] = s;
    } else if(threadIdx.x < VV){
        float s = 0.0f;
        for(int part=0; part<NPART; part++) s += g_spart[part*VV + threadIdx.x];
        g_s[threadIdx.x] = s;
    }
}

// ---------------- kernel 2b: Z, colsum(Z^2) normalize, Adj = Z^T Z --------
__global__ __launch_bounds__(256) void k_z(const float* __restrict__ W,
                                           const float* __restrict__ var){
    __shared__ float Zs[DD*33];
    __shared__ float s_s[VV], cs[VV];
    const int tid = threadIdx.x;   // = d
    if(tid < VV) s_s[tid] = g_s[tid];
    __syncthreads();

    #pragma unroll
    for(int v=0; v<VV; v++){
        int e = tid*VV + v;
        float sv = s_s[v];
        float z = (g_M[e] - W[e]*sv) * (1.0f/var[e]) / sv;
        Zs[tid*33 + v] = z;
    }
    __syncthreads();
    if(tid < VV){
        float acc = 0.0f;
        for(int d=0; d<DD; d++){ float z = Zs[d*33+tid]; acc = fmaf(z,z,acc); }
        cs[tid] = acc;
    }
    __syncthreads();
    #pragma unroll
    for(int v=0; v<VV; v++){
        float z = Zs[tid*33 + v] / cs[v];
        Zs[tid*33 + v] = z;
        g_Z[tid*VV + v] = z;
    }
    __syncthreads();
    for(int k=0;k<4;k++){
        int e = k*256 + tid;
        int i = e >> 5, j = e & 31;
        float acc = 0.0f;
        for(int d=0; d<DD; d++) acc = fmaf(Zs[d*33+i], Zs[d*33+j], acc);
        g_Adj[e] = acc;
    }
}

// ---------------- kernel 2c: T1 = Z^T weight ------------------------------
__global__ void k_t1(const float* __restrict__ weight){
    int v = blockIdx.x, f = threadIdx.x;
    float acc = 0.0f;
    for(int d=0; d<DD; d++) acc = fmaf(g_Z[d*VV+v], weight[d*NF+f], acc);
    g_T1[v*NF + f] = acc;
}
// ---------------- kernel 2d: Zo = relu(Adj @ T1) --------------------------
__global__ void k_zo(){
    int v = blockIdx.x, f = threadIdx.x;
    float acc = 0.0f;
    #pragma unroll
    for(int j=0;j<VV;j++) acc = fmaf(g_Adj[v*VV+j], g_T1[j*NF+f], acc);
    g_Zo[v*NF + f] = fmaxf(acc, 0.0f);
}

// ---------------- kernel 3: Xn = Q @ Zo -> out ----------------------------
// grid 4096, block 256 (8 warps); each warp: 8 points; lane owns f=l*4 and 128+l*4.
__global__ __launch_bounds__(256) void k_out(float* __restrict__ out){
    __shared__ __align__(16) float zo[VV*NF];       // 32 KB
    __shared__ __align__(16) float qts[8][264];     // per-warp [v][p] transpose

    const int tid = threadIdx.x, w = tid >> 5, l = tid & 31;
    for(int i=tid; i<VV*NF; i+=256) zo[i] = g_Zo[i];
    __syncthreads();

    const int pbase = blockIdx.x*64 + w*8;
    {   // stage Q transposed: lane l -> point l>>2, v-range (l&3)*8..+8
        const float4* src = (const float4*)(g_Q + (size_t)(pbase + (l>>2))*VV + (l&3)*8);
        float4 a = src[0], b = src[1];
        int p = l >> 2, vb = (l & 3)*8;
        float* dst = qts[w];
        dst[(vb+0)*8+p]=a.x; dst[(vb+1)*8+p]=a.y; dst[(vb+2)*8+p]=a.z; dst[(vb+3)*8+p]=a.w;
        dst[(vb+4)*8+p]=b.x; dst[(vb+5)*8+p]=b.y; dst[(vb+6)*8+p]=b.z; dst[(vb+7)*8+p]=b.w;
    }
    __syncwarp();

    ull acc[8][4];
    #pragma unroll
    for(int p=0;p<8;p++){ acc[p][0]=0ull; acc[p][1]=0ull; acc[p][2]=0ull; acc[p][3]=0ull; }

    #pragma unroll 4
    for(int v=0; v<VV; v++){
        ulonglong2 zA = *(const ulonglong2*)(zo + v*NF + l*4);        // f = l*4..+4
        ulonglong2 zB = *(const ulonglong2*)(zo + v*NF + 128 + l*4);  // f = 128+l*4..+4
        const float* qv = qts[w] + v*8;
        float4 qA = *(const float4*)(qv);
        float4 qB = *(const float4*)(qv+4);
        float qf[8] = {qA.x,qA.y,qA.z,qA.w,qB.x,qB.y,qB.z,qB.w};
        #pragma unroll
        for(int p=0;p<8;p++){
            ull qp = pk2(qf[p], qf[p]);
            acc[p][0] = f2fma(qp, zA.x, acc[p][0]);
            acc[p][1] = f2fma(qp, zA.y, acc[p][1]);
            acc[p][2] = f2fma(qp, zB.x, acc[p][2]);
            acc[p][3] = f2fma(qp, zB.y, acc[p][3]);
        }
    }
    #pragma unroll
    for(int p=0;p<8;p++){
        float2 f0=up2(acc[p][0]), f1=up2(acc[p][1]);
        float2 f2v=up2(acc[p][2]), f3=up2(acc[p][3]);
        float* base = out + (size_t)(pbase+p)*NF;
        *(float4*)(base + l*4)       = make_float4(f0.x,f0.y,f1.x,f1.y);
        *(float4*)(base + 128 + l*4) = make_float4(f2v.x,f2v.y,f3.x,f3.y);
    }
}

// ---------------- launch ---------------------------------------------------
extern "C" void kernel_launch(void* const* d_in, const int* in_sizes, int n_in,
                              void* d_out, int out_size){
    const float* X      = (const float*)d_in[0];
    const float* W      = (const float*)d_in[1];
    const float* var    = (const float*)d_in[2];
    const float* weight = (const float*)d_in[3];
    float* out = (float*)d_out;

    k_prep  <<<32, 256>>>(W, var);
    k_prep_c<<<1, 32>>>(W);
    k_qpass <<<HW/256, 128>>>(X);
    k_mpass <<<NPART, 256>>>(X);
    k_reduce<<<33, 256>>>();
    k_z     <<<1, 256>>>(W, var);
    k_t1    <<<VV, 256>>>(weight);
    k_zo    <<<VV, 256>>>();
    k_out   <<<HW/64, 256>>>(out);
}